// round 5
// baseline (speedup 1.0000x reference)
#include <cuda_runtime.h>
#include <cuda_bf16.h>
#include <math_constants.h>

#define B 128
#define P 8732
#define C 21
#define NEG_POS_RATIO 3
#define NT 1024
#define NWARP 32
#define KPT 9                 // ceil(8732/1024)
#define PC (P * C)            // 183372 floats per row
#define TILE_F4 168           // 32 anchors * 21 floats / 4
#define TILE_BYTES 2688

__device__ float g_acc[4];    // 0: pos_conf, 1: reg, 2: mask_sum, 3: neg_conf
__device__ int   g_done;

__device__ __forceinline__ unsigned f2key(float f) {
    unsigned b = __float_as_uint(f);
    return (b & 0x80000000u) ? ~b : (b | 0x80000000u);
}
__device__ __forceinline__ float key2f(unsigned k) {
    unsigned b = (k & 0x80000000u) ? (k & 0x7FFFFFFFu) : ~k;
    return __uint_as_float(b);
}
__device__ __forceinline__ float warp_sum_f(float v) {
    #pragma unroll
    for (int o = 16; o > 0; o >>= 1) v += __shfl_down_sync(0xFFFFFFFFu, v, o);
    return v;
}
__device__ __forceinline__ unsigned smem_u32(const void* p) {
    return (unsigned)__cvta_generic_to_shared(p);
}
// stage one 32-anchor conf tile into smem via cp.async (L1-bypass, no reg round-trip)
__device__ __forceinline__ void stage_tile(unsigned sdst, const float4* crow4,
                                           int f0, int lane) {
    #pragma unroll
    for (int kk = 0; kk < 6; kk++) {
        const int i4 = lane + kk * 32;
        if (i4 < TILE_F4 && (f0 + i4 * 4) < PC) {
            asm volatile("cp.async.cg.shared.global [%0], [%1], 16;\n"
                         :: "r"(sdst + i4 * 16), "l"(crow4 + (f0 >> 2) + i4));
        }
    }
}

extern __shared__ float s_stage[];   // NWARP * 2 * 672 floats = 172032 B

__global__ __launch_bounds__(NT, 1)
void k_all(const float* __restrict__ conf,
           const float* __restrict__ pred,
           const int*   __restrict__ labels,
           const float* __restrict__ gt,
           const float* __restrict__ mask,
           float* __restrict__ out) {
    const int b    = blockIdx.x;
    const int t    = threadIdx.x;
    const int wid  = t >> 5;
    const int lane = t & 31;

    __shared__ float    sredf[2][NWARP];
    __shared__ unsigned sredu[NWARP];
    __shared__ int      sredi[NWARP];
    __shared__ unsigned scnt12;
    __shared__ int      scnt3;
    __shared__ int      sk;
    __shared__ bool     sLast;

    const size_t  rb    = (size_t)b * P;
    const float*  crow  = conf + rb * C;
    const float4* crow4 = (const float4*)crow;       // row base 16B aligned
    float* wbuf0 = s_stage + wid * 2 * 672;          // warp-private double buffer
    const unsigned sb0 = smem_u32(wbuf0);
    const unsigned sb1 = sb0 + TILE_BYTES;

    unsigned keys[KPT];
    float posc = 0.0f, regl = 0.0f, msum = 0.0f;
    int   npos = 0;

    // ---------------- prologue: prefetch tile 0 + its labels/mask ----------------
    stage_tile(sb0, crow4, (wid * 32) * C, lane);
    asm volatile("cp.async.commit_group;\n");
    int   lab_c = labels[rb + wid * 32 + lane];      // tile 0 always in range
    float mk_c  = mask[rb + wid * 32 + lane];

    // ---------------- pipelined streaming loop ----------------
    #pragma unroll
    for (int i = 0; i < KPT; i++) {
        // issue next tile into the other buffer
        const int a0n  = (i + 1) * NT + wid * 32;
        if (i + 1 < KPT)
            stage_tile(((i + 1) & 1) ? sb1 : sb0, crow4, a0n * C, lane);
        asm volatile("cp.async.commit_group;\n");
        // prefetch next labels/mask
        int lab_n = 0; float mk_n = 0.0f;
        const int idxn = a0n + lane;
        if (i + 1 < KPT && idxn < P) {
            lab_n = labels[rb + idxn];
            mk_n  = mask[rb + idxn];
        }
        // current tile ready (only next tile's group still outstanding)
        asm volatile("cp.async.wait_group 1;\n");
        __syncwarp();

        const int idx = i * NT + wid * 32 + lane;
        unsigned key = 0u;
        if (idx < P) {
            const float* c = (float*)((i & 1) ? (wbuf0 + 672) : wbuf0) + lane * C;
            float v[C];
            #pragma unroll
            for (int j = 0; j < C; j++) v[j] = c[j];   // stride 21: conflict-free

            float m = v[0];
            #pragma unroll
            for (int j = 1; j < C; j++) m = fmaxf(m, v[j]);
            float s = 0.0f;
            #pragma unroll
            for (int j = 0; j < C; j++) s += __expf(v[j] - m);
            const float lse = __logf(s) + m;

            msum += mk_c;
            if (lab_c > 0) {
                npos++;
                float clab = v[0];
                #pragma unroll
                for (int j = 1; j < C; j++) clab = (lab_c == j) ? v[j] : clab;
                posc += mk_c * (lse - clab);
                const size_t gi = rb + idx;
                const float4 pv = *(const float4*)(pred + gi * 4);
                const float4 gv = *(const float4*)(gt   + gi * 4);
                float r = 0.0f, d, ad;
                d = pv.x - gv.x; ad = fabsf(d); r += (ad < 1.0f) ? 0.5f * d * d : ad - 0.5f;
                d = pv.y - gv.y; ad = fabsf(d); r += (ad < 1.0f) ? 0.5f * d * d : ad - 0.5f;
                d = pv.z - gv.z; ad = fabsf(d); r += (ad < 1.0f) ? 0.5f * d * d : ad - 0.5f;
                d = pv.w - gv.w; ad = fabsf(d); r += (ad < 1.0f) ? 0.5f * d * d : ad - 0.5f;
                regl += mk_c * r;
            } else {
                key = f2key(lse - v[0]);               // bg loss >= 0
            }
        }
        keys[i] = key;
        lab_c = lab_n; mk_c = mk_n;
    }

    // ---------------- block reduce scalars ----------------
    posc = warp_sum_f(posc);
    regl = warp_sum_f(regl);
    msum = warp_sum_f(msum);
    npos = __reduce_add_sync(0xFFFFFFFFu, npos);
    if (lane == 0) {
        sredf[0][wid] = posc; sredf[1][wid] = regl; sredu[wid] = __float_as_uint(msum);
        sredi[wid] = npos;
    }
    __syncthreads();
    if (wid == 0) {
        float a0 = sredf[0][lane], a1 = sredf[1][lane], a2 = __uint_as_float(sredu[lane]);
        int   a3 = sredi[lane];
        a0 = warp_sum_f(a0); a1 = warp_sum_f(a1); a2 = warp_sum_f(a2);
        a3 = __reduce_add_sync(0xFFFFFFFFu, a3);
        if (lane == 0) {
            atomicAdd(&g_acc[0], a0);
            atomicAdd(&g_acc[1], a1);
            atomicAdd(&g_acc[2], a2);
            sk = a3 * NEG_POS_RATIO;
        }
    }
    __syncthreads();
    const int k = sk;

    // ---------------- phase 2: exact top-k sum, 2-bit radix (16 passes) ----------------
    float negsum = 0.0f;
    if (k > 0) {
        unsigned prefix = 0u;
        for (int bit = 30; bit >= 0; bit -= 2) {
            const unsigned c1 = prefix | (1u << bit);
            const unsigned c2 = prefix | (2u << bit);
            const unsigned c3 = prefix | (3u << bit);
            unsigned p12 = 0; int n3 = 0;
            #pragma unroll
            for (int i = 0; i < KPT; i++) {
                p12 += (keys[i] >= c1) + ((unsigned)(keys[i] >= c2) << 16);
                n3  += (keys[i] >= c3);
            }
            p12 = __reduce_add_sync(0xFFFFFFFFu, p12);
            n3  = __reduce_add_sync(0xFFFFFFFFu, n3);
            if (lane == 0) { sredu[wid] = p12; sredi[wid] = n3; }
            __syncthreads();
            if (wid == 0) {
                unsigned u = __reduce_add_sync(0xFFFFFFFFu, sredu[lane]);
                int      v = __reduce_add_sync(0xFFFFFFFFu, sredi[lane]);
                if (lane == 0) { scnt12 = u; scnt3 = v; }
            }
            __syncthreads();
            const int n1 = (int)(scnt12 & 0xFFFFu);
            const int n2 = (int)(scnt12 >> 16);
            prefix = (scnt3 >= k) ? c3 : (n2 >= k) ? c2 : (n1 >= k) ? c1 : prefix;
        }

        int cgt = 0; float sgt = 0.0f;
        #pragma unroll
        for (int i = 0; i < KPT; i++) {
            if (keys[i] > prefix) { cgt++; sgt += key2f(keys[i]); }
        }
        cgt = __reduce_add_sync(0xFFFFFFFFu, cgt);
        sgt = warp_sum_f(sgt);
        if (lane == 0) { sredi[wid] = cgt; sredf[0][wid] = sgt; }
        __syncthreads();
        if (t == 0) {
            int ctot = 0; float stot = 0.0f;
            #pragma unroll
            for (int w = 0; w < NWARP; w++) { ctot += sredi[w]; stot += sredf[0][w]; }
            const float tv = (prefix != 0u) ? key2f(prefix) : 0.0f;
            negsum = stot + (float)(k - ctot) * tv;
        }
    }
    if (t == 0 && negsum != 0.0f) atomicAdd(&g_acc[3], negsum);

    // ---------------- last block finalizes + resets ----------------
    if (t == 0) {
        __threadfence();
        const int prev = atomicAdd(&g_done, 1);
        sLast = (prev == B - 1);
    }
    __syncthreads();
    if (sLast && t == 0) {
        volatile float* a = g_acc;
        const float inv = 1.0f / a[2];
        out[0] = a[1] * inv;
        out[1] = (a[0] + a[3]) * inv;
        a[0] = 0.0f; a[1] = 0.0f; a[2] = 0.0f; a[3] = 0.0f;
        g_done = 0;
    }
}

extern "C" void kernel_launch(void* const* d_in, const int* in_sizes, int n_in,
                              void* d_out, int out_size) {
    const float* conf   = (const float*)d_in[0];
    const float* pred   = (const float*)d_in[1];
    const int*   labels = (const int*)d_in[2];
    const float* gt     = (const float*)d_in[3];
    const float* mask   = (const float*)d_in[4];
    float* out = (float*)d_out;

    const int smem = NWARP * 2 * 672 * sizeof(float);    // 172032 B
    cudaFuncSetAttribute(k_all, cudaFuncAttributeMaxDynamicSharedMemorySize, smem);
    k_all<<<B, NT, smem>>>(conf, pred, labels, gt, mask, out);
}

// round 6
// speedup vs baseline: 1.0536x; 1.0536x over previous
#include <cuda_runtime.h>
#include <cuda_bf16.h>
#include <math_constants.h>

#define B 128
#define P 8732
#define C 21
#define NEG_POS_RATIO 3
#define NT 1024
#define NWARP 32
#define KPT 9                 // ceil(8732/1024)
#define PC (P * C)            // 183372 floats per row
#define TILE_FLOATS 672       // 32 anchors * 21
#define TILE_BYTES 2688

__device__ float g_acc[4];    // 0: pos_conf, 1: reg, 2: mask_sum, 3: neg_conf
__device__ int   g_done;

__device__ __forceinline__ unsigned f2key(float f) {
    unsigned b = __float_as_uint(f);
    return (b & 0x80000000u) ? ~b : (b | 0x80000000u);
}
__device__ __forceinline__ float key2f(unsigned k) {
    unsigned b = (k & 0x80000000u) ? (k & 0x7FFFFFFFu) : ~k;
    return __uint_as_float(b);
}
__device__ __forceinline__ float warp_sum_f(float v) {
    #pragma unroll
    for (int o = 16; o > 0; o >>= 1) v += __shfl_down_sync(0xFFFFFFFFu, v, o);
    return v;
}
__device__ __forceinline__ unsigned smem_u32(const void* p) {
    return (unsigned)__cvta_generic_to_shared(p);
}
// one bulk async copy per warp-tile (elected lane). bytes must be >0, 16B-multiple.
__device__ __forceinline__ void issue_bulk(unsigned mbar, unsigned sdst,
                                           const float* gsrc, int bytes, int lane) {
    if (lane == 0 && bytes > 0) {
        asm volatile("mbarrier.arrive.expect_tx.shared.b64 _, [%0], %1;"
                     :: "r"(mbar), "r"((unsigned)bytes) : "memory");
        asm volatile("cp.async.bulk.shared::cta.global.mbarrier::complete_tx::bytes "
                     "[%0], [%1], %2, [%3];"
                     :: "r"(sdst), "l"(gsrc), "r"((unsigned)bytes), "r"(mbar) : "memory");
    }
}
__device__ __forceinline__ void mbar_wait(unsigned mbar, unsigned phase) {
    asm volatile(
        "{\n\t.reg .pred P1;\n"
        "WL%=:\n\t"
        "mbarrier.try_wait.parity.shared::cta.b64 P1, [%0], %1, 0x989680;\n\t"
        "@!P1 bra WL%=;\n\t}"
        :: "r"(mbar), "r"(phase) : "memory");
}

extern __shared__ float s_stage[];   // NWARP * 2 * 672 floats = 172032 B

__global__ __launch_bounds__(NT, 1)
void k_all(const float* __restrict__ conf,
           const float* __restrict__ pred,
           const int*   __restrict__ labels,
           const float* __restrict__ gt,
           const float* __restrict__ mask,
           float* __restrict__ out) {
    const int b    = blockIdx.x;
    const int t    = threadIdx.x;
    const int wid  = t >> 5;
    const int lane = t & 31;

    __shared__ unsigned long long s_mbar[NWARP * 2];
    __shared__ float    sredf[2][NWARP];
    __shared__ unsigned sredu[NWARP];
    __shared__ int      sredi[NWARP];
    __shared__ unsigned scnt12;
    __shared__ int      scnt3;
    __shared__ int      sk;
    __shared__ bool     sLast;

    const size_t rb   = (size_t)b * P;
    const float* crow = conf + rb * C;
    float*   wbuf = s_stage + wid * 2 * TILE_FLOATS;   // warp-private double buffer
    const unsigned sb0 = smem_u32(wbuf);
    const unsigned mb0 = smem_u32(&s_mbar[wid * 2]);
    const unsigned mb1 = mb0 + 8;

    // init per-warp mbarriers
    if (lane == 0) {
        asm volatile("mbarrier.init.shared.b64 [%0], 1;" :: "r"(mb0) : "memory");
        asm volatile("mbarrier.init.shared.b64 [%0], 1;" :: "r"(mb1) : "memory");
        asm volatile("fence.proxy.async.shared::cta;" ::: "memory");
    }
    __syncwarp();

    unsigned keys[KPT];
    float posc = 0.0f, regl = 0.0f, msum = 0.0f;
    int   npos = 0;

    // prologue: tile 0 (always full)
    issue_bulk(mb0, sb0, crow + (wid * 32) * C, TILE_BYTES, lane);

    #pragma unroll
    for (int i = 0; i < KPT; i++) {
        // issue next tile into the other buffer
        if (i + 1 < KPT) {
            const int f0n = ((i + 1) * NT + wid * 32) * C;
            const int bn  = min(TILE_BYTES, (PC - f0n) * 4);
            issue_bulk(((i + 1) & 1) ? mb1 : mb0,
                       sb0 + ((i + 1) & 1) * TILE_BYTES, crow + f0n, bn, lane);
        }
        // overlap: small loads for the current tile
        const int idx = i * NT + wid * 32 + lane;
        int lab = 0; float mk = 0.0f;
        if (idx < P) { lab = labels[rb + idx]; mk = mask[rb + idx]; }

        // wait for current tile (skip if this warp's tile is fully OOB)
        const int f0c = (i * NT + wid * 32) * C;
        if (f0c < PC) mbar_wait((i & 1) ? mb1 : mb0, (unsigned)((i >> 1) & 1));

        unsigned key = 0u;
        if (idx < P) {
            const float* c = wbuf + (i & 1) * TILE_FLOATS + lane * C;
            float v[C];
            #pragma unroll
            for (int j = 0; j < C; j++) v[j] = c[j];   // stride 21: conflict-free

            float m = v[0];
            #pragma unroll
            for (int j = 1; j < C; j++) m = fmaxf(m, v[j]);
            float s = 0.0f;
            #pragma unroll
            for (int j = 0; j < C; j++) s += __expf(v[j] - m);
            const float lse = __logf(s) + m;

            msum += mk;
            if (lab > 0) {
                npos++;
                float clab = v[0];
                #pragma unroll
                for (int j = 1; j < C; j++) clab = (lab == j) ? v[j] : clab;
                posc += mk * (lse - clab);
                const size_t gi = rb + idx;
                const float4 pv = *(const float4*)(pred + gi * 4);
                const float4 gv = *(const float4*)(gt   + gi * 4);
                float r = 0.0f, d, ad;
                d = pv.x - gv.x; ad = fabsf(d); r += (ad < 1.0f) ? 0.5f * d * d : ad - 0.5f;
                d = pv.y - gv.y; ad = fabsf(d); r += (ad < 1.0f) ? 0.5f * d * d : ad - 0.5f;
                d = pv.z - gv.z; ad = fabsf(d); r += (ad < 1.0f) ? 0.5f * d * d : ad - 0.5f;
                d = pv.w - gv.w; ad = fabsf(d); r += (ad < 1.0f) ? 0.5f * d * d : ad - 0.5f;
                regl += mk * r;
            } else {
                key = f2key(lse - v[0]);               // bg loss >= 0
            }
        }
        keys[i] = key;
    }

    // ---------------- block reduce scalars ----------------
    posc = warp_sum_f(posc);
    regl = warp_sum_f(regl);
    msum = warp_sum_f(msum);
    npos = __reduce_add_sync(0xFFFFFFFFu, npos);
    if (lane == 0) {
        sredf[0][wid] = posc; sredf[1][wid] = regl; sredu[wid] = __float_as_uint(msum);
        sredi[wid] = npos;
    }
    __syncthreads();
    if (wid == 0) {
        float a0 = sredf[0][lane], a1 = sredf[1][lane], a2 = __uint_as_float(sredu[lane]);
        int   a3 = sredi[lane];
        a0 = warp_sum_f(a0); a1 = warp_sum_f(a1); a2 = warp_sum_f(a2);
        a3 = __reduce_add_sync(0xFFFFFFFFu, a3);
        if (lane == 0) {
            atomicAdd(&g_acc[0], a0);
            atomicAdd(&g_acc[1], a1);
            atomicAdd(&g_acc[2], a2);
            sk = a3 * NEG_POS_RATIO;
        }
    }
    __syncthreads();
    const int k = sk;

    // ---------------- phase 2: exact top-k sum, 2-bit radix (16 passes) ----------------
    float negsum = 0.0f;
    if (k > 0) {
        unsigned prefix = 0u;
        for (int bit = 30; bit >= 0; bit -= 2) {
            const unsigned c1 = prefix | (1u << bit);
            const unsigned c2 = prefix | (2u << bit);
            const unsigned c3 = prefix | (3u << bit);
            unsigned p12 = 0; int n3 = 0;
            #pragma unroll
            for (int i = 0; i < KPT; i++) {
                p12 += (keys[i] >= c1) + ((unsigned)(keys[i] >= c2) << 16);
                n3  += (keys[i] >= c3);
            }
            p12 = __reduce_add_sync(0xFFFFFFFFu, p12);
            n3  = __reduce_add_sync(0xFFFFFFFFu, n3);
            if (lane == 0) { sredu[wid] = p12; sredi[wid] = n3; }
            __syncthreads();
            if (wid == 0) {
                unsigned u = __reduce_add_sync(0xFFFFFFFFu, sredu[lane]);
                int      v = __reduce_add_sync(0xFFFFFFFFu, sredi[lane]);
                if (lane == 0) { scnt12 = u; scnt3 = v; }
            }
            __syncthreads();
            const int n1 = (int)(scnt12 & 0xFFFFu);
            const int n2 = (int)(scnt12 >> 16);
            prefix = (scnt3 >= k) ? c3 : (n2 >= k) ? c2 : (n1 >= k) ? c1 : prefix;
        }

        int cgt = 0; float sgt = 0.0f;
        #pragma unroll
        for (int i = 0; i < KPT; i++) {
            if (keys[i] > prefix) { cgt++; sgt += key2f(keys[i]); }
        }
        cgt = __reduce_add_sync(0xFFFFFFFFu, cgt);
        sgt = warp_sum_f(sgt);
        if (lane == 0) { sredi[wid] = cgt; sredf[0][wid] = sgt; }
        __syncthreads();
        if (t == 0) {
            int ctot = 0; float stot = 0.0f;
            #pragma unroll
            for (int w = 0; w < NWARP; w++) { ctot += sredi[w]; stot += sredf[0][w]; }
            const float tv = (prefix != 0u) ? key2f(prefix) : 0.0f;
            negsum = stot + (float)(k - ctot) * tv;
        }
    }
    if (t == 0 && negsum != 0.0f) atomicAdd(&g_acc[3], negsum);

    // ---------------- last block finalizes + resets ----------------
    if (t == 0) {
        __threadfence();
        const int prev = atomicAdd(&g_done, 1);
        sLast = (prev == B - 1);
    }
    __syncthreads();
    if (sLast && t == 0) {
        volatile float* a = g_acc;
        const float inv = 1.0f / a[2];
        out[0] = a[1] * inv;
        out[1] = (a[0] + a[3]) * inv;
        a[0] = 0.0f; a[1] = 0.0f; a[2] = 0.0f; a[3] = 0.0f;
        g_done = 0;
    }
}

extern "C" void kernel_launch(void* const* d_in, const int* in_sizes, int n_in,
                              void* d_out, int out_size) {
    const float* conf   = (const float*)d_in[0];
    const float* pred   = (const float*)d_in[1];
    const int*   labels = (const int*)d_in[2];
    const float* gt     = (const float*)d_in[3];
    const float* mask   = (const float*)d_in[4];
    float* out = (float*)d_out;

    const int smem = NWARP * 2 * TILE_FLOATS * sizeof(float);   // 172032 B
    cudaFuncSetAttribute(k_all, cudaFuncAttributeMaxDynamicSharedMemorySize, smem);
    k_all<<<B, NT, smem>>>(conf, pred, labels, gt, mask, out);
}